// round 17
// baseline (speedup 1.0000x reference)
#include <cuda_runtime.h>
#include <cuda_fp16.h>
#include <cstdint>
#include <cstring>

#define NN 40000
#define NE 640000
#define DD 128
#define LL 3
#define GRID 148
#define NTILES (NN / 64)          // 625 exact
#define XSTH (64 * 72)            // halves per X stage (row stride 72)

// ---------------- scratch (static __device__, no allocation) ----------------
__device__ __align__(256) float  g_A[NN * DD];     // psi-top out, fp32 (by dst)
__device__ __align__(256) __half g_Bh[NN * DD];    // psi-bot out, fp16 (by src)
__device__ __align__(256) __half g_aggh[NN * DD];  // scatter-mean, fp16
__device__ __align__(256) float  g_xa[NN * DD];    // x fp32 (residual path)
__device__ __align__(256) float  g_xb[NN * DD];
__device__ __align__(256) __half g_xh0[NN * DD];   // fp16(x input)
__device__ __align__(256) __half g_xha[NN * DD];   // fp16 x double buffers
__device__ __align__(256) __half g_xhb[NN * DD];
__device__ float g_invdeg[NN];
__device__ int   g_deg[NN];
__device__ int   g_rowptr[NN + 1];
__device__ int   g_cursor[NN];
__device__ int   g_esrc[NE];

__device__ __forceinline__ float* resolve_buf(int id) {   // fp32
    switch (id) {
        case 0: return g_A;
        case 3: return g_xa;
        case 4: return g_xb;
        default: return nullptr;
    }
}
__device__ __forceinline__ __half* resolve_hbuf(int id) { // fp16
    switch (id) {
        case 0: return g_xh0;
        case 1: return g_xha;
        case 2: return g_xhb;
        case 3: return g_aggh;
        default: return nullptr;
    }
}

__device__ __forceinline__ uint32_t h2u(__half2 h) {
    uint32_t u;
    memcpy(&u, &h, 4);
    return u;
}

#define CP16(dst_u32, src_ptr) \
    asm volatile("cp.async.cg.shared.global [%0], [%1], 16;\n" \
                 :: "r"(dst_u32), "l"(src_ptr))

// ---------------- init: zero deg + x -> fp16 ----------------
__global__ void init_kernel(const float* __restrict__ x) {
    int i = blockIdx.x * blockDim.x + threadIdx.x;
    if (i < NN) g_deg[i] = 0;
    int j = i * 8;
    if (j < NN * DD) {
        float4 v0 = *(const float4*)&x[j];
        float4 v1 = *(const float4*)&x[j + 4];
        uint4 u;
        u.x = h2u(__floats2half2_rn(v0.x, v0.y));
        u.y = h2u(__floats2half2_rn(v0.z, v0.w));
        u.z = h2u(__floats2half2_rn(v1.x, v1.y));
        u.w = h2u(__floats2half2_rn(v1.z, v1.w));
        *(uint4*)&g_xh0[j] = u;
    }
}

// ---------------- CSR build (1 edge/thread — best measured) ----------------
__global__ void hist_kernel(const int* __restrict__ ei) {
    int e = blockIdx.x * blockDim.x + threadIdx.x;
    if (e < NE) {
        unsigned d = (unsigned)ei[NE + e];
        if (d < NN) atomicAdd(&g_deg[d], 1);
    }
}

__global__ void scan_kernel() {
    const int PER = 40;
    int tid = threadIdx.x;
    int lane = tid & 31, w = tid >> 5;
    int base = tid * PER;

    int total = 0;
    for (int j = 0; j < PER; j++) {
        int i = base + j;
        if (i < NN) total += g_deg[i];
    }
    int incl = total;
    #pragma unroll
    for (int off = 1; off < 32; off <<= 1) {
        int t = __shfl_up_sync(0xFFFFFFFFu, incl, off);
        if (lane >= off) incl += t;
    }
    __shared__ int wsum[32];
    if (lane == 31) wsum[w] = incl;
    __syncthreads();
    if (w == 0) {
        int v = wsum[lane];
        #pragma unroll
        for (int off = 1; off < 32; off <<= 1) {
            int t = __shfl_up_sync(0xFFFFFFFFu, v, off);
            if (lane >= off) v += t;
        }
        wsum[lane] = v;
    }
    __syncthreads();
    int run = incl - total + (w > 0 ? wsum[w - 1] : 0);
    for (int j = 0; j < PER; j++) {
        int i = base + j;
        if (i < NN) {
            int v = g_deg[i];
            g_rowptr[i] = run;
            g_cursor[i] = run;
            g_invdeg[i] = 1.0f / (float)(v > 1 ? v : 1);
            run += v;
        }
    }
    if (tid == 1023) g_rowptr[NN] = run;
}

__global__ void fill_kernel(const int* __restrict__ ei) {
    int e = blockIdx.x * blockDim.x + threadIdx.x;
    if (e < NE) {
        unsigned dst = (unsigned)ei[NE + e];
        unsigned src = (unsigned)ei[e];
        if (dst < NN && src < NN) {
            int pos = atomicAdd(&g_cursor[dst], 1);
            g_esrc[pos] = (int)src;
        }
    }
}

// ---------------- edge aggregation v3: 2 nodes/warp, half-warp uint4 -------
__global__ void agg_kernel() {
    int gt = blockIdx.x * blockDim.x + threadIdx.x;
    int node = (gt >> 5) * 2 + ((threadIdx.x >> 4) & 1);
    int lane8 = threadIdx.x & 15;
    if (node >= NN) return;
    int c = lane8 << 3;                       // 8 channels per lane
    const float4 a0 = *(const float4*)&g_A[node * DD + c];
    const float4 a1 = *(const float4*)&g_A[node * DD + c + 4];
    float4 s0 = make_float4(0.f, 0.f, 0.f, 0.f);
    float4 s1 = make_float4(0.f, 0.f, 0.f, 0.f);
    int e0 = g_rowptr[node];
    int e1 = g_rowptr[node + 1];
    #pragma unroll 4
    for (int e = e0; e < e1; ++e) {
        int s = g_esrc[e];
        uint4 hb = *(const uint4*)&g_Bh[s * DD + c];   // 8 halves = 16B
        float2 b0 = __half22float2(*(__half2*)&hb.x);
        float2 b1 = __half22float2(*(__half2*)&hb.y);
        float2 b2 = __half22float2(*(__half2*)&hb.z);
        float2 b3 = __half22float2(*(__half2*)&hb.w);
        s0.x += fmaxf(a0.x + b0.x, 0.f); s0.y += fmaxf(a0.y + b0.y, 0.f);
        s0.z += fmaxf(a0.z + b1.x, 0.f); s0.w += fmaxf(a0.w + b1.y, 0.f);
        s1.x += fmaxf(a1.x + b2.x, 0.f); s1.y += fmaxf(a1.y + b2.y, 0.f);
        s1.z += fmaxf(a1.z + b3.x, 0.f); s1.w += fmaxf(a1.w + b3.y, 0.f);
    }
    float id = g_invdeg[node];
    uint4 o;
    o.x = h2u(__floats2half2_rn(s0.x * id, s0.y * id));
    o.y = h2u(__floats2half2_rn(s0.z * id, s0.w * id));
    o.z = h2u(__floats2half2_rn(s1.x * id, s1.y * id));
    o.w = h2u(__floats2half2_rn(s1.z * id, s1.w * id));
    *(uint4*)&g_aggh[node * DD + c] = o;
}

// ---------------- psi1: persistent W-resident pipelined fp16 GEMM -----------
__global__ void __launch_bounds__(512) psi_gemm(
    const float* __restrict__ W1, const float* __restrict__ W2,
    const float* __restrict__ bias, int xh1_id)
{
    constexpr int WSH = 264;
    constexpr int NF = 4;

    extern __shared__ __align__(16) unsigned char sh_raw[];
    __half*   Xsm  = (__half*)sh_raw;                       // [4][64][72]
    uint32_t* Whsm = (uint32_t*)(sh_raw + 4 * XSTH * 2);    // [64][264]

    const __half* X1 = resolve_hbuf(xh1_id);

    int tid = threadIdx.x;
    int lane = tid & 31;
    int wid = tid >> 5;
    int warp_m = wid >> 3;
    int warp_n = wid & 7;
    int g = lane >> 2;
    int tg = lane & 3;
    int b = blockIdx.x;

    uint32_t xbase;
    { uint64_t tmp = __cvta_generic_to_shared(Xsm); xbase = (uint32_t)tmp; }

    #pragma unroll
    for (int i = 0; i < 8; i++) {
        int f = tid + i * 512;
        int kh = f >> 6;
        int c4 = (f & 63) << 2;
        const float* Wm = (c4 < 128) ? W1 : W2;
        int cc = c4 & 127;
        float4 v0 = *(const float4*)(Wm + (2 * kh) * 128 + cc);
        float4 v1 = *(const float4*)(Wm + (2 * kh + 1) * 128 + cc);
        uint4 u;
        u.x = h2u(__floats2half2_rn(v0.x, v1.x));
        u.y = h2u(__floats2half2_rn(v0.y, v1.y));
        u.z = h2u(__floats2half2_rn(v0.z, v1.z));
        u.w = h2u(__floats2half2_rn(v0.w, v1.w));
        *(uint4*)&Whsm[kh * WSH + c4] = u;
    }

    float bv[NF][2];
    #pragma unroll
    for (int nf = 0; nf < NF; nf++) {
        int colg = warp_n * 32 + nf * 8 + tg * 2;
        bv[nf][0] = (colg < 128) ? bias[colg] : 0.f;
        bv[nf][1] = (colg < 128) ? bias[colg + 1] : 0.f;
    }

    int nt = (NTILES - b + GRID - 1) / GRID;
    int TOTAL = nt * 2;

    int xrow = tid >> 3;
    int xkq = (tid & 7) << 3;

    auto issue = [&](int ci) {
        int t = b + (ci >> 1) * GRID;
        int k0 = (ci & 1) * 64;
        const __half* src = X1 + (size_t)(t * 64 + xrow) * 128 + k0 + xkq;
        uint32_t dst = xbase + ((ci & 3) * XSTH + xrow * 72 + xkq) * 2;
        CP16(dst, src);
        asm volatile("cp.async.commit_group;\n" ::);
    };

    issue(0); issue(1); if (TOTAL > 2) issue(2);

    float C[2][NF][4];
    #pragma unroll
    for (int i = 0; i < 2; i++)
        #pragma unroll
        for (int j = 0; j < NF; j++)
            #pragma unroll
            for (int q = 0; q < 4; q++) C[i][j][q] = 0.f;

    int lm_row = lane & 15;
    int lm_c8 = (lane >> 4) << 3;

    for (int ci = 0; ci < TOTAL; ci++) {
        int nxt = ci + 3; if (nxt > TOTAL - 1) nxt = TOTAL - 1;
        issue(nxt);
        asm volatile("cp.async.wait_group 3;\n" ::: "memory");
        __syncthreads();

        int k = ci & 1;
        int khchunk = k * 32;
        uint32_t stg = xbase + (ci & 3) * XSTH * 2;

        #pragma unroll
        for (int kg = 0; kg < 4; kg++) {
            int kk = kg * 16;
            uint32_t a[2][4];
            #pragma unroll
            for (int mf = 0; mf < 2; mf++) {
                int r = warp_m * 32 + mf * 16 + lm_row;
                uint32_t addr = stg + (r * 72 + kk + lm_c8) * 2;
                asm volatile(
                    "ldmatrix.sync.aligned.m8n8.x4.shared.b16 {%0,%1,%2,%3}, [%4];"
                    : "=r"(a[mf][0]), "=r"(a[mf][1]), "=r"(a[mf][2]), "=r"(a[mf][3])
                    : "r"(addr));
            }
            int khb = khchunk + kg * 8;
            #pragma unroll
            for (int nf = 0; nf < NF; nf++) {
                int col = warp_n * 32 + nf * 8 + g;
                uint32_t b0 = Whsm[(khb + tg) * WSH + col];
                uint32_t b1 = Whsm[(khb + tg + 4) * WSH + col];
                #pragma unroll
                for (int mf = 0; mf < 2; mf++) {
                    asm volatile(
                        "mma.sync.aligned.m16n8k16.row.col.f32.f16.f16.f32 "
                        "{%0,%1,%2,%3}, {%4,%5,%6,%7}, {%8,%9}, {%0,%1,%2,%3};"
                        : "+f"(C[mf][nf][0]), "+f"(C[mf][nf][1]),
                          "+f"(C[mf][nf][2]), "+f"(C[mf][nf][3])
                        : "r"(a[mf][0]), "r"(a[mf][1]), "r"(a[mf][2]), "r"(a[mf][3]),
                          "r"(b0), "r"(b1));
                }
            }
        }

        if (k == 1) {
            int t = b + (ci >> 1) * GRID;
            int m0 = t * 64;
            #pragma unroll
            for (int nf = 0; nf < NF; nf++) {
                int colg = warp_n * 32 + nf * 8 + tg * 2;
                #pragma unroll
                for (int mf = 0; mf < 2; mf++) {
                    #pragma unroll
                    for (int h = 0; h < 2; h++) {
                        int m = m0 + warp_m * 32 + mf * 16 + g + h * 8;
                        float v0 = C[mf][nf][h * 2 + 0] + bv[nf][0];
                        float v1 = C[mf][nf][h * 2 + 1] + bv[nf][1];
                        if (colg < 128) {
                            *(float2*)&g_A[(size_t)m * 128 + colg] = make_float2(v0, v1);
                        } else {
                            *(__half2*)&g_Bh[(size_t)m * 128 + (colg - 128)] =
                                __floats2half2_rn(v0, v1);
                        }
                        C[mf][nf][h * 2 + 0] = 0.f;
                        C[mf][nf][h * 2 + 1] = 0.f;
                    }
                }
            }
        }
        __syncthreads();
    }
}

// ---------------- fused phi + (psi | dp) ------------------------------------
template <int P2>
__global__ void __launch_bounds__(512) phi_fused(
    const float* __restrict__ ResExt,
    const float* __restrict__ Wphi1, const float* __restrict__ Wphi2,
    const float* __restrict__ phi_bias,
    const float* __restrict__ Wp2a, const float* __restrict__ Wp2b,
    const float* __restrict__ p2_bias,
    float* __restrict__ OutExt,
    int xh1_id, int res_id, int out32_id, int outh_id)
{
    constexpr int WSH = 136;
    constexpr int NF2 = (P2 == 0) ? 4 : 2;
    constexpr int WSH2 = (P2 == 0) ? 264 : 136;
    constexpr int WPHI_OFF = 4 * XSTH * 2;
    constexpr int WP2_OFF = WPHI_OFF + 128 * WSH * 4;
    constexpr int TILE_OFF = WP2_OFF + 64 * WSH2 * 4;
    constexpr int TS = 136;

    extern __shared__ __align__(16) unsigned char sh_raw[];
    __half*   Xsm    = (__half*)sh_raw;
    uint32_t* Wphism = (uint32_t*)(sh_raw + WPHI_OFF);
    uint32_t* Wp2sm  = (uint32_t*)(sh_raw + WP2_OFF);
    __half*   Tile   = (__half*)(sh_raw + TILE_OFF);

    const __half* X1 = resolve_hbuf(xh1_id);
    const __half* X2 = g_aggh;
    const float* res = (res_id < 0) ? ResExt : resolve_buf(res_id);
    float* out32 = resolve_buf(out32_id);
    __half* outh = (outh_id >= 0) ? resolve_hbuf(outh_id) : nullptr;

    int tid = threadIdx.x;
    int lane = tid & 31;
    int wid = tid >> 5;
    int warp_m = wid >> 3;
    int warp_n = wid & 7;
    int g = lane >> 2;
    int tg = lane & 3;
    int b = blockIdx.x;

    uint32_t xbase, tbase;
    { uint64_t tmp = __cvta_generic_to_shared(Xsm); xbase = (uint32_t)tmp; }
    { uint64_t tmp = __cvta_generic_to_shared(Tile); tbase = (uint32_t)tmp; }

    #pragma unroll
    for (int i = 0; i < 8; i++) {
        int f = tid + i * 512;
        int kh = f >> 5;
        int c4 = (f & 31) << 2;
        const float* Wm = (kh < 64) ? Wphi1 : Wphi2;
        int kk = kh & 63;
        float4 v0 = *(const float4*)(Wm + (2 * kk) * 128 + c4);
        float4 v1 = *(const float4*)(Wm + (2 * kk + 1) * 128 + c4);
        uint4 u;
        u.x = h2u(__floats2half2_rn(v0.x, v1.x));
        u.y = h2u(__floats2half2_rn(v0.y, v1.y));
        u.z = h2u(__floats2half2_rn(v0.z, v1.z));
        u.w = h2u(__floats2half2_rn(v0.w, v1.w));
        *(uint4*)&Wphism[kh * WSH + c4] = u;
    }
    if (P2 == 0) {
        #pragma unroll
        for (int i = 0; i < 8; i++) {
            int f = tid + i * 512;
            int kh = f >> 6;
            int c4 = (f & 63) << 2;
            const float* Wm = (c4 < 128) ? Wp2a : Wp2b;
            int cc = c4 & 127;
            float4 v0 = *(const float4*)(Wm + (2 * kh) * 128 + cc);
            float4 v1 = *(const float4*)(Wm + (2 * kh + 1) * 128 + cc);
            uint4 u;
            u.x = h2u(__floats2half2_rn(v0.x, v1.x));
            u.y = h2u(__floats2half2_rn(v0.y, v1.y));
            u.z = h2u(__floats2half2_rn(v0.z, v1.z));
            u.w = h2u(__floats2half2_rn(v0.w, v1.w));
            *(uint4*)&Wp2sm[kh * WSH2 + c4] = u;
        }
    } else {
        #pragma unroll
        for (int i = 0; i < 4; i++) {
            int f = tid + i * 512;
            int kh = f >> 5;
            int c4 = (f & 31) << 2;
            float4 v0 = *(const float4*)(Wp2a + (2 * kh) * 128 + c4);
            float4 v1 = *(const float4*)(Wp2a + (2 * kh + 1) * 128 + c4);
            uint4 u;
            u.x = h2u(__floats2half2_rn(v0.x, v1.x));
            u.y = h2u(__floats2half2_rn(v0.y, v1.y));
            u.z = h2u(__floats2half2_rn(v0.z, v1.z));
            u.w = h2u(__floats2half2_rn(v0.w, v1.w));
            *(uint4*)&Wp2sm[kh * WSH2 + c4] = u;
        }
    }

    float bv[2][2];
    #pragma unroll
    for (int nf = 0; nf < 2; nf++) {
        int colg = warp_n * 16 + nf * 8 + tg * 2;
        bv[nf][0] = phi_bias[colg];
        bv[nf][1] = phi_bias[colg + 1];
    }
    float bv2[NF2][2];
    #pragma unroll
    for (int nf = 0; nf < NF2; nf++) {
        int colg = warp_n * (NF2 * 8) + nf * 8 + tg * 2;
        if (P2 == 0) {
            bv2[nf][0] = (colg < 128) ? p2_bias[colg] : 0.f;
            bv2[nf][1] = (colg < 128) ? p2_bias[colg + 1] : 0.f;
        } else {
            bv2[nf][0] = p2_bias[colg];
            bv2[nf][1] = p2_bias[colg + 1];
        }
    }

    int nt = (NTILES - b + GRID - 1) / GRID;
    int TOTAL = nt * 4;

    int xrow = tid >> 3;
    int xkq = (tid & 7) << 3;

    auto issue = [&](int ci) {
        int t = b + (ci >> 2) * GRID;
        int k = ci & 3;
        const __half* Xp = (k >= 2) ? X2 : X1;
        int k0 = (k & 1) * 64;
        const __half* src = Xp + (size_t)(t * 64 + xrow) * 128 + k0 + xkq;
        uint32_t dst = xbase + ((ci & 3) * XSTH + xrow * 72 + xkq) * 2;
        CP16(dst, src);
        asm volatile("cp.async.commit_group;\n" ::);
    };

    issue(0); issue(1); issue(2);

    float C[2][2][4];
    #pragma unroll
    for (int i = 0; i < 2; i++)
        #pragma unroll
        for (int j = 0; j < 2; j++)
            #pragma unroll
            for (int q = 0; q < 4; q++) C[i][j][q] = 0.f;

    int lm_row = lane & 15;
    int lm_c8 = (lane >> 4) << 3;

    for (int ci = 0; ci < TOTAL; ci++) {
        int nxt = ci + 3; if (nxt > TOTAL - 1) nxt = TOTAL - 1;
        issue(nxt);
        asm volatile("cp.async.wait_group 3;\n" ::: "memory");
        __syncthreads();

        int k = ci & 3;
        int khchunk = (k >> 1) * 64 + (k & 1) * 32;
        uint32_t stg = xbase + (ci & 3) * XSTH * 2;

        #pragma unroll
        for (int kg = 0; kg < 4; kg++) {
            int kk = kg * 16;
            uint32_t a[2][4];
            #pragma unroll
            for (int mf = 0; mf < 2; mf++) {
                int r = warp_m * 32 + mf * 16 + lm_row;
                uint32_t addr = stg + (r * 72 + kk + lm_c8) * 2;
                asm volatile(
                    "ldmatrix.sync.aligned.m8n8.x4.shared.b16 {%0,%1,%2,%3}, [%4];"
                    : "=r"(a[mf][0]), "=r"(a[mf][1]), "=r"(a[mf][2]), "=r"(a[mf][3])
                    : "r"(addr));
            }
            int khb = khchunk + kg * 8;
            #pragma unroll
            for (int nf = 0; nf < 2; nf++) {
                int col = warp_n * 16 + nf * 8 + g;
                uint32_t b0 = Wphism[(khb + tg) * WSH + col];
                uint32_t b1 = Wphism[(khb + tg + 4) * WSH + col];
                #pragma unroll
                for (int mf = 0; mf < 2; mf++) {
                    asm volatile(
                        "mma.sync.aligned.m16n8k16.row.col.f32.f16.f16.f32 "
                        "{%0,%1,%2,%3}, {%4,%5,%6,%7}, {%8,%9}, {%0,%1,%2,%3};"
                        : "+f"(C[mf][nf][0]), "+f"(C[mf][nf][1]),
                          "+f"(C[mf][nf][2]), "+f"(C[mf][nf][3])
                        : "r"(a[mf][0]), "r"(a[mf][1]), "r"(a[mf][2]), "r"(a[mf][3]),
                          "r"(b0), "r"(b1));
                }
            }
        }

        if (k == 3) {
            int t = b + (ci >> 2) * GRID;
            int m0 = t * 64;
            #pragma unroll
            for (int nf = 0; nf < 2; nf++) {
                int colg = warp_n * 16 + nf * 8 + tg * 2;
                #pragma unroll
                for (int mf = 0; mf < 2; mf++) {
                    #pragma unroll
                    for (int h = 0; h < 2; h++) {
                        int ml = warp_m * 32 + mf * 16 + g + h * 8;
                        int m = m0 + ml;
                        float v0 = C[mf][nf][h * 2 + 0] + bv[nf][0];
                        float v1 = C[mf][nf][h * 2 + 1] + bv[nf][1];
                        v0 = fmaxf(v0, 0.f); v1 = fmaxf(v1, 0.f);
                        float2 r = *(const float2*)&res[(size_t)m * 128 + colg];
                        v0 += r.x; v1 += r.y;
                        *(float2*)&out32[(size_t)m * 128 + colg] = make_float2(v0, v1);
                        __half2 hv = __floats2half2_rn(v0, v1);
                        if (outh)
                            *(__half2*)&outh[(size_t)m * 128 + colg] = hv;
                        *(__half2*)&Tile[ml * TS + colg] = hv;
                        C[mf][nf][h * 2 + 0] = 0.f;
                        C[mf][nf][h * 2 + 1] = 0.f;
                    }
                }
            }
            __syncthreads();
            float C2[2][NF2][4];
            #pragma unroll
            for (int i = 0; i < 2; i++)
                #pragma unroll
                for (int j = 0; j < NF2; j++)
                    #pragma unroll
                    for (int q = 0; q < 4; q++) C2[i][j][q] = 0.f;

            #pragma unroll
            for (int kg = 0; kg < 8; kg++) {
                int kk = kg * 16;
                uint32_t a[2][4];
                #pragma unroll
                for (int mf = 0; mf < 2; mf++) {
                    int r = warp_m * 32 + mf * 16 + lm_row;
                    uint32_t addr = tbase + (r * TS + kk + lm_c8) * 2;
                    asm volatile(
                        "ldmatrix.sync.aligned.m8n8.x4.shared.b16 {%0,%1,%2,%3}, [%4];"
                        : "=r"(a[mf][0]), "=r"(a[mf][1]), "=r"(a[mf][2]), "=r"(a[mf][3])
                        : "r"(addr));
                }
                int khb = kg * 8;
                #pragma unroll
                for (int nf = 0; nf < NF2; nf++) {
                    int col = warp_n * (NF2 * 8) + nf * 8 + g;
                    uint32_t b0 = Wp2sm[(khb + tg) * WSH2 + col];
                    uint32_t b1 = Wp2sm[(khb + tg + 4) * WSH2 + col];
                    #pragma unroll
                    for (int mf = 0; mf < 2; mf++) {
                        asm volatile(
                            "mma.sync.aligned.m16n8k16.row.col.f32.f16.f16.f32 "
                            "{%0,%1,%2,%3}, {%4,%5,%6,%7}, {%8,%9}, {%0,%1,%2,%3};"
                            : "+f"(C2[mf][nf][0]), "+f"(C2[mf][nf][1]),
                              "+f"(C2[mf][nf][2]), "+f"(C2[mf][nf][3])
                            : "r"(a[mf][0]), "r"(a[mf][1]), "r"(a[mf][2]), "r"(a[mf][3]),
                              "r"(b0), "r"(b1));
                    }
                }
            }
            #pragma unroll
            for (int nf = 0; nf < NF2; nf++) {
                int colg = warp_n * (NF2 * 8) + nf * 8 + tg * 2;
                #pragma unroll
                for (int mf = 0; mf < 2; mf++) {
                    #pragma unroll
                    for (int h = 0; h < 2; h++) {
                        int m = m0 + warp_m * 32 + mf * 16 + g + h * 8;
                        float v0 = C2[mf][nf][h * 2 + 0] + bv2[nf][0];
                        float v1 = C2[mf][nf][h * 2 + 1] + bv2[nf][1];
                        if (P2 == 0) {
                            if (colg < 128) {
                                *(float2*)&g_A[(size_t)m * 128 + colg] =
                                    make_float2(v0, v1);
                            } else {
                                *(__half2*)&g_Bh[(size_t)m * 128 + (colg - 128)] =
                                    __floats2half2_rn(v0, v1);
                            }
                        } else {
                            *(float2*)&OutExt[(size_t)m * 128 + colg] =
                                make_float2(v0, v1);
                        }
                    }
                }
            }
        }
        __syncthreads();
    }
}

// ---------------- launch ----------------
extern "C" void kernel_launch(void* const* d_in, const int* in_sizes, int n_in,
                              void* d_out, int out_size) {
    const float* x     = (const float*)d_in[0];
    const int*   ei    = (const int*)d_in[1];
    const float* psi_w = (const float*)d_in[2];
    const float* psi_b = (const float*)d_in[3];
    const float* phi_w = (const float*)d_in[4];
    const float* phi_b = (const float*)d_in[5];
    const float* dp_w  = (const float*)d_in[6];
    const float* dp_b  = (const float*)d_in[7];
    float* out = (float*)d_out;

    const int XBYTES   = 4 * XSTH * 2;
    const int PSI_SM   = XBYTES + 64 * 264 * 4;
    const int FUSE_PSI = XBYTES + 128 * 136 * 4 + 64 * 264 * 4 + 64 * 136 * 2;
    const int FUSE_DP  = XBYTES + 128 * 136 * 4 + 64 * 136 * 4 + 64 * 136 * 2;

    cudaFuncSetAttribute(psi_gemm,
                         cudaFuncAttributeMaxDynamicSharedMemorySize, PSI_SM);
    cudaFuncSetAttribute(phi_fused<0>,
                         cudaFuncAttributeMaxDynamicSharedMemorySize, FUSE_PSI);
    cudaFuncSetAttribute(phi_fused<1>,
                         cudaFuncAttributeMaxDynamicSharedMemorySize, FUSE_DP);

    init_kernel<<<(NN * DD / 8 + 255) / 256, 256>>>(x);
    hist_kernel<<<(NE + 255) / 256, 256>>>(ei);
    scan_kernel<<<1, 1024>>>();
    fill_kernel<<<(NE + 255) / 256, 256>>>(ei);

    const int AGG_BLOCKS = (NN / 2 * 32 + 255) / 256;   // 2 nodes per warp

    const float* psiT0 = psi_w;
    psi_gemm<<<GRID, 512, PSI_SM>>>(psiT0, psiT0 + 128 * 128, psi_b, 0);

    int xh_in = 0;
    int res_id = -1;
    for (int l = 0; l < LL; l++) {
        agg_kernel<<<AGG_BLOCKS, 256>>>();
        const float* phiT = phi_w + (size_t)l * 256 * 128;
        const float* phiB = phiT + 128 * 128;
        if (l < LL - 1) {
            const float* psiT = psi_w + (size_t)(l + 1) * 256 * 128;
            const float* psiB = psiT + 128 * 128;
            int xo32 = 3 + (l & 1);
            int xo16 = 1 + (l & 1);
            phi_fused<0><<<GRID, 512, FUSE_PSI>>>(
                x, phiT, phiB, phi_b + (size_t)l * 128,
                psiT, psiB, psi_b + (size_t)(l + 1) * 128, nullptr,
                xh_in, res_id, xo32, xo16);
            xh_in = xo16;
            res_id = xo32;
        } else {
            phi_fused<1><<<GRID, 512, FUSE_DP>>>(
                x, phiT, phiB, phi_b + (size_t)l * 128,
                dp_w, nullptr, dp_b, out,
                xh_in, res_id, 3 + (l & 1), -1);
        }
    }
}